// round 3
// baseline (speedup 1.0000x reference)
#include <cuda_runtime.h>
#include <cuda_bf16.h>
#include <stdint.h>

#define NMAX 100000
#define EMAX 1000000

// ---- static device scratch ----
__device__ __align__(16) int   g_count[NMAX];
__device__ __align__(16) int   g_start[NMAX];
__device__ __align__(16) int   g_cursor[NMAX];
__device__ __align__(16) int   g_bsum[128];
__device__ __align__(16) float g_degf[NMAX];
__device__ __align__(16) float g_dinv[NMAX];
__device__ __align__(16) int   g_esrc[EMAX];
__device__ __align__(16) float g_enorm[EMAX];
__device__ __align__(16) float g_H[3][NMAX * 64];   // [0]=S scratch, [1],[2]=h buffers
__device__ __align__(16) float g_F[NMAX];           // final gemv result
__device__ int g_is64;                              // edge_index dtype flag

// edge_index accessor: idx in [0, 2E)
__device__ __forceinline__ int edge_at(const void* ei, int idx)
{
    if (g_is64) return (int)((const long long*)ei)[idx];
    return ((const int*)ei)[idx];
}

// ---------------------------------------------------------------------------
// dtype probe: int64 interpretation of first 64 entries must all be in [0, n).
// If buffer is actually int32, high words hold random indices -> detect.
// Safe: reads <= 512 bytes of an >= 4MB buffer.
// ---------------------------------------------------------------------------
__global__ void probe_kernel(const void* ei, int n)
{
    const long long* e64 = (const long long*)ei;
    int ok = 1;
    for (int k = 0; k < 64; k++) {
        long long v = e64[k];
        if (v < 0 || v >= n) { ok = 0; break; }
    }
    g_is64 = ok;
}

// ---------------------------------------------------------------------------
// CSR / norm build
// ---------------------------------------------------------------------------
__global__ void init_kernel(int n)
{
    int i = blockIdx.x * blockDim.x + threadIdx.x;
    if (i < n) { g_count[i] = 0; g_degf[i] = 1.0f; }  // self-loop weight folded in
}

__global__ void hist_kernel(const void* __restrict__ ei,
                            const float* __restrict__ ew, int E, int n)
{
    int e = blockIdx.x * blockDim.x + threadIdx.x;
    if (e < E) {
        int c = edge_at(ei, E + e);
        if ((unsigned)c < (unsigned)n) {
            atomicAdd(&g_count[c], 1);
            atomicAdd(&g_degf[c], ew[e]);
        }
    }
}

// scan step 1: per-block (1024 elems) exclusive scan + block sums
__global__ void scan1_kernel(int n)
{
    __shared__ int sd[256];
    int t = threadIdx.x;
    int base = blockIdx.x * 1024 + t * 4;
    int v0 = (base + 0 < n) ? g_count[base + 0] : 0;
    int v1 = (base + 1 < n) ? g_count[base + 1] : 0;
    int v2 = (base + 2 < n) ? g_count[base + 2] : 0;
    int v3 = (base + 3 < n) ? g_count[base + 3] : 0;
    int tsum = v0 + v1 + v2 + v3;
    sd[t] = tsum;
    __syncthreads();
    int x = tsum;
    for (int off = 1; off < 256; off <<= 1) {
        int y = (t >= off) ? sd[t - off] : 0;
        __syncthreads();
        x += y;
        sd[t] = x;
        __syncthreads();
    }
    int run = x - tsum;
    if (base + 0 < n) g_start[base + 0] = run;
    run += v0;
    if (base + 1 < n) g_start[base + 1] = run;
    run += v1;
    if (base + 2 < n) g_start[base + 2] = run;
    run += v2;
    if (base + 3 < n) g_start[base + 3] = run;
    if (t == 255) g_bsum[blockIdx.x] = x;
}

// scan step 2: exclusive scan of <=128 block sums
__global__ void scan2_kernel(int nb)
{
    __shared__ int sd[128];
    int t = threadIdx.x;
    int v = (t < nb) ? g_bsum[t] : 0;
    sd[t] = v;
    __syncthreads();
    int x = v;
    for (int off = 1; off < 128; off <<= 1) {
        int y = (t >= off) ? sd[t - off] : 0;
        __syncthreads();
        x += y;
        sd[t] = x;
        __syncthreads();
    }
    if (t < nb) g_bsum[t] = x - v;
}

// scan step 3: add block offsets, init cursor, compute dinv
__global__ void scan3_kernel(int n)
{
    int i = blockIdx.x * blockDim.x + threadIdx.x;
    if (i < n) {
        int val = g_start[i] + g_bsum[i >> 10];
        g_start[i] = val;
        g_cursor[i] = val;
        g_dinv[i] = rsqrtf(g_degf[i]);
    }
}

__global__ void build_kernel(const void* __restrict__ ei,
                             const float* __restrict__ ew, int E, int n)
{
    int e = blockIdx.x * blockDim.x + threadIdx.x;
    if (e < E) {
        int r = edge_at(ei, e);
        int c = edge_at(ei, E + e);
        if ((unsigned)r < (unsigned)n && (unsigned)c < (unsigned)n) {
            float nm = g_dinv[r] * ew[e] * g_dinv[c];
            int p = atomicAdd(&g_cursor[c], 1);
            if ((unsigned)p < (unsigned)EMAX) {
                g_esrc[p] = r;
                g_enorm[p] = nm;
            }
        }
    }
}

// ---------------------------------------------------------------------------
// Dense GEMM: g_H[dst] = h @ W, h = hext (harness input) or g_H[src]
// ---------------------------------------------------------------------------
__global__ void __launch_bounds__(256) gemm64_kernel(const float* __restrict__ hext,
                                                     int src, int dst,
                                                     const float* __restrict__ W, int n)
{
    __shared__ float sW[4096];
    for (int i = threadIdx.x; i < 4096; i += 256) sW[i] = W[i];
    __syncthreads();
    int row = blockIdx.x * 256 + threadIdx.x;
    if (row >= n) return;

    const float* h = hext ? hext : g_H[src];
    const float4* hr = reinterpret_cast<const float4*>(h + (size_t)row * 64);
    float acc[64];
#pragma unroll
    for (int j = 0; j < 64; j++) acc[j] = 0.0f;

#pragma unroll 4
    for (int k4 = 0; k4 < 16; k4++) {
        float4 xv = __ldg(hr + k4);
        const float4* w0 = reinterpret_cast<const float4*>(sW + (k4 * 4 + 0) * 64);
        const float4* w1 = reinterpret_cast<const float4*>(sW + (k4 * 4 + 1) * 64);
        const float4* w2 = reinterpret_cast<const float4*>(sW + (k4 * 4 + 2) * 64);
        const float4* w3 = reinterpret_cast<const float4*>(sW + (k4 * 4 + 3) * 64);
#pragma unroll
        for (int j = 0; j < 16; j++) {
            float4 a = w0[j], b = w1[j], c = w2[j], d = w3[j];
            acc[4 * j + 0] = fmaf(xv.x, a.x, fmaf(xv.y, b.x, fmaf(xv.z, c.x, fmaf(xv.w, d.x, acc[4 * j + 0]))));
            acc[4 * j + 1] = fmaf(xv.x, a.y, fmaf(xv.y, b.y, fmaf(xv.z, c.y, fmaf(xv.w, d.y, acc[4 * j + 1]))));
            acc[4 * j + 2] = fmaf(xv.x, a.z, fmaf(xv.y, b.z, fmaf(xv.z, c.z, fmaf(xv.w, d.z, acc[4 * j + 2]))));
            acc[4 * j + 3] = fmaf(xv.x, a.w, fmaf(xv.y, b.w, fmaf(xv.z, c.w, fmaf(xv.w, d.w, acc[4 * j + 3]))));
        }
    }

    float4* o = reinterpret_cast<float4*>(g_H[dst] + (size_t)row * 64);
#pragma unroll
    for (int j = 0; j < 16; j++)
        o[j] = make_float4(acc[4 * j + 0], acc[4 * j + 1], acc[4 * j + 2], acc[4 * j + 3]);
}

// ---------------------------------------------------------------------------
// Aggregation: warp per node, 2 floats per lane.
// ---------------------------------------------------------------------------
__global__ void __launch_bounds__(256) agg_kernel(const float* __restrict__ bias,
                                                  int src, int resid, int dst,
                                                  int n, int do_relu)
{
    int wid = (blockIdx.x * blockDim.x + threadIdx.x) >> 5;
    int lane = threadIdx.x & 31;
    if (wid >= n) return;
    int i = wid;

    const float2* hw2 = reinterpret_cast<const float2*>(g_H[src]);
    float di = g_dinv[i];
    float selfn = di * di;
    float2 v = hw2[i * 32 + lane];
    float ax = selfn * v.x, ay = selfn * v.y;
    float a1x = 0.f, a1y = 0.f, a2x = 0.f, a2y = 0.f, a3x = 0.f, a3y = 0.f;

    int e = g_start[i];
    int end = e + g_count[i];
    for (; e + 4 <= end; e += 4) {
        int s0 = g_esrc[e], s1 = g_esrc[e + 1], s2 = g_esrc[e + 2], s3 = g_esrc[e + 3];
        float n0 = g_enorm[e], n1 = g_enorm[e + 1], n2 = g_enorm[e + 2], n3 = g_enorm[e + 3];
        float2 v0 = hw2[s0 * 32 + lane];
        float2 v1 = hw2[s1 * 32 + lane];
        float2 v2 = hw2[s2 * 32 + lane];
        float2 v3 = hw2[s3 * 32 + lane];
        ax  += n0 * v0.x; ay  += n0 * v0.y;
        a1x += n1 * v1.x; a1y += n1 * v1.y;
        a2x += n2 * v2.x; a2y += n2 * v2.y;
        a3x += n3 * v3.x; a3y += n3 * v3.y;
    }
    for (; e < end; e++) {
        int s0 = g_esrc[e];
        float n0 = g_enorm[e];
        float2 v0 = hw2[s0 * 32 + lane];
        ax += n0 * v0.x; ay += n0 * v0.y;
    }
    ax += a1x + a2x + a3x;
    ay += a1y + a2y + a3y;

    float2 bb = reinterpret_cast<const float2*>(bias)[lane];
    ax += bb.x; ay += bb.y;
    if (resid >= 0) {
        float2 r = reinterpret_cast<const float2*>(g_H[resid])[i * 32 + lane];
        ax += r.x; ay += r.y;
    }
    if (do_relu) { ax = fmaxf(ax, 0.f); ay = fmaxf(ay, 0.f); }
    reinterpret_cast<float2*>(g_H[dst])[i * 32 + lane] = make_float2(ax, ay);
}

// ---------------------------------------------------------------------------
// Final layer: gemv (64 -> 1), then scalar aggregation
// ---------------------------------------------------------------------------
__global__ void gemvf_kernel(int src, const float* __restrict__ Wf, int n)
{
    __shared__ float sW[64];
    if (threadIdx.x < 64) sW[threadIdx.x] = Wf[threadIdx.x];
    __syncthreads();
    int i = blockIdx.x * blockDim.x + threadIdx.x;
    if (i >= n) return;
    const float4* hr = reinterpret_cast<const float4*>(g_H[src] + (size_t)i * 64);
    float acc = 0.f;
#pragma unroll
    for (int k = 0; k < 16; k++) {
        float4 hv = __ldg(hr + k);
        acc += hv.x * sW[4 * k + 0] + hv.y * sW[4 * k + 1]
             + hv.z * sW[4 * k + 2] + hv.w * sW[4 * k + 3];
    }
    g_F[i] = acc;
}

__global__ void agg_final_kernel(const float* __restrict__ bf,
                                 float* __restrict__ out, int n)
{
    int i = blockIdx.x * blockDim.x + threadIdx.x;
    if (i >= n) return;
    float di = g_dinv[i];
    float acc = di * di * g_F[i];
    float a1 = 0.f, a2 = 0.f, a3 = 0.f;
    int e = g_start[i];
    int end = e + g_count[i];
    for (; e + 4 <= end; e += 4) {
        acc += g_enorm[e]     * g_F[g_esrc[e]];
        a1  += g_enorm[e + 1] * g_F[g_esrc[e + 1]];
        a2  += g_enorm[e + 2] * g_F[g_esrc[e + 2]];
        a3  += g_enorm[e + 3] * g_F[g_esrc[e + 3]];
    }
    for (; e < end; e++) acc += g_enorm[e] * g_F[g_esrc[e]];
    out[i] = acc + a1 + a2 + a3 + bf[0];
}

// ---------------------------------------------------------------------------
// Launch
// ---------------------------------------------------------------------------
extern "C" void kernel_launch(void* const* d_in, const int* in_sizes, int n_in,
                              void* d_out, int out_size)
{
    const float* x    = (const float*)d_in[0];
    const void*  ei   = d_in[1];                 // int32 or int64, auto-detected
    const float* ew   = (const float*)d_in[2];
    const float* W_in = (const float*)d_in[4];
    const float* b_in = (const float*)d_in[5];
    const float* W1   = (const float*)d_in[6];
    const float* b1   = (const float*)d_in[7];
    const float* W2   = (const float*)d_in[8];
    const float* b2   = (const float*)d_in[9];
    const float* Wf   = (const float*)d_in[10];
    const float* bf   = (const float*)d_in[11];
    float* out = (float*)d_out;

    int n = in_sizes[0] / 64;
    int E = in_sizes[2];

    int nbN  = (n + 255) / 256;
    int nbE  = (E + 255) / 256;
    int nbSc = (n + 1023) / 1024;     // <= 128
    int nbAg = (n + 7) / 8;           // warp per node
    int nbGm = (n + 255) / 256;

    // --- dtype probe + norm + CSR build ---
    probe_kernel<<<1, 1>>>(ei, n);
    init_kernel<<<nbN, 256>>>(n);
    hist_kernel<<<nbE, 256>>>(ei, ew, E, n);
    scan1_kernel<<<nbSc, 256>>>(n);
    scan2_kernel<<<1, 128>>>(nbSc);
    scan3_kernel<<<nbN, 256>>>(n);
    build_kernel<<<nbE, 256>>>(ei, ew, E, n);

    // --- layer 1: h1 = relu(conv(x, W_in, b_in)) -> H[1] ---
    gemm64_kernel<<<nbGm, 256>>>(x, 0, 0, W_in, n);
    agg_kernel<<<nbAg, 256>>>(b_in, 0, -1, 1, n, 1);

    // --- layer 2: h2 = relu(conv(h1, W1, b1) + h1) -> H[2] ---
    gemm64_kernel<<<nbGm, 256>>>(nullptr, 1, 0, W1, n);
    agg_kernel<<<nbAg, 256>>>(b1, 0, 1, 2, n, 1);

    // --- layer 3: h3 = relu(conv(h2, W2, b2) + h2) -> H[1] ---
    gemm64_kernel<<<nbGm, 256>>>(nullptr, 2, 0, W2, n);
    agg_kernel<<<nbAg, 256>>>(b2, 0, 2, 1, n, 1);

    // --- final: out = conv(h3, Wf, bf) ---
    gemvf_kernel<<<nbGm, 256>>>(1, Wf, n);
    agg_final_kernel<<<nbN, 256>>>(bf, out, n);
}

// round 4
// speedup vs baseline: 1.0722x; 1.0722x over previous
#include <cuda_runtime.h>
#include <cuda_fp16.h>
#include <stdint.h>

#define NMAX 100000
#define EMAX 1000000

typedef unsigned long long ull;

// ---- static device scratch ----
__device__ __align__(16) ull    g_packed[NMAX];     // count<<40 | deg_fixed(2^-28)
__device__ __align__(16) int    g_start[NMAX];
__device__ __align__(16) int    g_cursor[NMAX];
__device__ __align__(16) int    g_bsum[128];
__device__ __align__(16) float  g_dinv[NMAX];
__device__ __align__(16) uint2  g_edge[EMAX];       // (src, norm bits)
__device__ __align__(16) __half2 g_Shw[NMAX * 32];  // hw scratch, fp16
__device__ __align__(16) float  g_H[2][NMAX * 64];  // h1 / h2 buffers (fp32)
__device__ __align__(16) float  g_F[NMAX];          // final gemv result
__device__ int g_is64;

// ---------------------------------------------------------------------------
// helpers
// ---------------------------------------------------------------------------
__device__ __forceinline__ int edge_at(const void* ei, int idx)
{
    if (g_is64) return (int)((const long long*)ei)[idx];
    return ((const int*)ei)[idx];
}

__device__ __forceinline__ ull ffma2(ull a, ull b, ull c)
{
    ull d;
    asm("fma.rn.f32x2 %0, %1, %2, %3;" : "=l"(d) : "l"(a), "l"(b), "l"(c));
    return d;
}

__device__ __forceinline__ ull pack2(float lo, float hi)
{
    ull d;
    asm("mov.b64 %0, {%1, %2};" : "=l"(d) : "r"(__float_as_uint(lo)), "r"(__float_as_uint(hi)));
    return d;
}

__device__ __forceinline__ float2 unpack2(ull v)
{
    unsigned lo, hi;
    asm("mov.b64 {%0, %1}, %2;" : "=r"(lo), "=r"(hi) : "l"(v));
    return make_float2(__uint_as_float(lo), __uint_as_float(hi));
}

__device__ __forceinline__ unsigned smem_u32(const void* p)
{
    unsigned a;
    asm("{ .reg .u64 t; cvta.to.shared.u64 t, %1; cvt.u32.u64 %0, t; }" : "=r"(a) : "l"(p));
    return a;
}

// ---------------------------------------------------------------------------
// init + dtype probe (block 0 / warp 0 does a 32-wide ballot probe)
// ---------------------------------------------------------------------------
__global__ void init_kernel(const void* ei, int E, int n)
{
    if (blockIdx.x == 0 && threadIdx.x < 32) {
        long long v = ((const long long*)ei)[threadIdx.x];
        unsigned ok = __ballot_sync(0xffffffffu, v >= 0 && v < (long long)n);
        if (threadIdx.x == 0) g_is64 = (ok == 0xffffffffu) ? 1 : 0;
    }
    int i = blockIdx.x * blockDim.x + threadIdx.x;
    if (i < n) g_packed[i] = (ull)1 << 28;   // self-loop: count 0, deg 1.0 in 2^-28 fixed
}

// ---------------------------------------------------------------------------
// histogram: single packed 64-bit atomic per edge
// ---------------------------------------------------------------------------
__global__ void hist_kernel(const void* __restrict__ ei,
                            const float* __restrict__ ew, int E, int n)
{
    int e = blockIdx.x * blockDim.x + threadIdx.x;
    if (e < E) {
        int c = edge_at(ei, E + e);
        if ((unsigned)c < (unsigned)n) {
            ull add = ((ull)1 << 40) + __float2ull_rn(ew[e] * 268435456.0f);
            atomicAdd(&g_packed[c], add);
        }
    }
}

// scan step 1: per-block (1024 elems) exclusive scan + block sums
__global__ void scan1_kernel(int n)
{
    __shared__ int sd[256];
    int t = threadIdx.x;
    int base = blockIdx.x * 1024 + t * 4;
    int v0 = (base + 0 < n) ? (int)(g_packed[base + 0] >> 40) : 0;
    int v1 = (base + 1 < n) ? (int)(g_packed[base + 1] >> 40) : 0;
    int v2 = (base + 2 < n) ? (int)(g_packed[base + 2] >> 40) : 0;
    int v3 = (base + 3 < n) ? (int)(g_packed[base + 3] >> 40) : 0;
    int tsum = v0 + v1 + v2 + v3;
    sd[t] = tsum;
    __syncthreads();
    int x = tsum;
    for (int off = 1; off < 256; off <<= 1) {
        int y = (t >= off) ? sd[t - off] : 0;
        __syncthreads();
        x += y;
        sd[t] = x;
        __syncthreads();
    }
    int run = x - tsum;
    if (base + 0 < n) g_start[base + 0] = run;
    run += v0;
    if (base + 1 < n) g_start[base + 1] = run;
    run += v1;
    if (base + 2 < n) g_start[base + 2] = run;
    run += v2;
    if (base + 3 < n) g_start[base + 3] = run;
    if (t == 255) g_bsum[blockIdx.x] = x;
}

// scan steps 2+3 fused: every block re-scans the <=128 block sums in smem,
// then applies offsets, inits cursor, computes dinv.
__global__ void scan23_kernel(int n, int nb)
{
    __shared__ int sb[256];
    __shared__ int sbx[256];
    int t = threadIdx.x;
    int v = (t < nb) ? g_bsum[t] : 0;
    sb[t] = v;
    __syncthreads();
    int x = v;
    for (int off = 1; off < 256; off <<= 1) {
        int y = (t >= off) ? sb[t - off] : 0;
        __syncthreads();
        x += y;
        sb[t] = x;
        __syncthreads();
    }
    sbx[t] = x - v;   // exclusive
    __syncthreads();

    int i = blockIdx.x * blockDim.x + t;
    if (i < n) {
        int val = g_start[i] + sbx[i >> 10];
        g_start[i] = val;
        g_cursor[i] = val;
        ull pk = g_packed[i];
        float deg = (float)(pk & (((ull)1 << 40) - 1)) * (1.0f / 268435456.0f);
        g_dinv[i] = rsqrtf(deg);
    }
}

__global__ void build_kernel(const void* __restrict__ ei,
                             const float* __restrict__ ew, int E, int n)
{
    int e = blockIdx.x * blockDim.x + threadIdx.x;
    if (e < E) {
        int r = edge_at(ei, e);
        int c = edge_at(ei, E + e);
        if ((unsigned)r < (unsigned)n && (unsigned)c < (unsigned)n) {
            float nm = g_dinv[r] * ew[e] * g_dinv[c];
            int p = atomicAdd(&g_cursor[c], 1);
            if ((unsigned)p < (unsigned)EMAX)
                g_edge[p] = make_uint2((unsigned)r, __float_as_uint(nm));
        }
    }
}

// ---------------------------------------------------------------------------
// Dense GEMM via packed f32x2: g_Shw = (hext or g_H[src]) @ W, fp16 output
// ---------------------------------------------------------------------------
__global__ void __launch_bounds__(256) gemm64_kernel(const float* __restrict__ hext,
                                                     int src,
                                                     const float* __restrict__ W, int n)
{
    __shared__ float sW[4096];
    for (int i = threadIdx.x; i < 4096; i += 256) sW[i] = W[i];
    __syncthreads();
    int row = blockIdx.x * 256 + threadIdx.x;
    if (row >= n) return;

    const float* h = hext ? hext : g_H[src];
    const float4* hr = reinterpret_cast<const float4*>(h + (size_t)row * 64);
    unsigned swaddr = smem_u32(sW);

    ull acc[32];
#pragma unroll
    for (int j = 0; j < 32; j++) acc[j] = 0ull;

    for (int k4 = 0; k4 < 16; k4++) {     // not unrolled: keep body in L0 I$
        float4 xv = __ldg(hr + k4);
#pragma unroll
        for (int kk = 0; kk < 4; kk++) {
            float xk = (kk == 0) ? xv.x : (kk == 1) ? xv.y : (kk == 2) ? xv.z : xv.w;
            ull x2 = pack2(xk, xk);
            unsigned wrow = swaddr + (unsigned)(k4 * 4 + kk) * 256;
#pragma unroll
            for (int j = 0; j < 16; j++) {
                ull w01, w23;
                asm("ld.shared.v2.u64 {%0, %1}, [%2];"
                    : "=l"(w01), "=l"(w23) : "r"(wrow + j * 16));
                acc[2 * j]     = ffma2(x2, w01, acc[2 * j]);
                acc[2 * j + 1] = ffma2(x2, w23, acc[2 * j + 1]);
            }
        }
    }

    // convert 32 f32 pairs -> 32 half2 -> 8 uint4 stores (128B/row)
    unsigned hu[32];
#pragma unroll
    for (int j = 0; j < 32; j++) {
        float2 p = unpack2(acc[j]);
        __half2 hh = __floats2half2_rn(p.x, p.y);
        hu[j] = *reinterpret_cast<unsigned*>(&hh);
    }
    uint4* o = reinterpret_cast<uint4*>(g_Shw + (size_t)row * 32);
#pragma unroll
    for (int q = 0; q < 8; q++)
        o[q] = make_uint4(hu[4 * q], hu[4 * q + 1], hu[4 * q + 2], hu[4 * q + 3]);
}

// ---------------------------------------------------------------------------
// Aggregation (layers 1,2): warp per node, half2 gather (one 128B line/edge)
// g_H[dst][i] = relu( sum_e nm*hw[src] + dinv^2*hw[i] + bias (+ resid) )
// ---------------------------------------------------------------------------
__global__ void __launch_bounds__(256) agg_kernel(const float* __restrict__ bias,
                                                  int resid, int dst, int n)
{
    int wid = (blockIdx.x * blockDim.x + threadIdx.x) >> 5;
    int lane = threadIdx.x & 31;
    if (wid >= n) return;
    int i = wid;

    float di = g_dinv[i];
    float selfn = di * di;
    float2 v = __half22float2(g_Shw[(size_t)i * 32 + lane]);
    float ax = selfn * v.x, ay = selfn * v.y;
    float a1x = 0.f, a1y = 0.f, a2x = 0.f, a2y = 0.f, a3x = 0.f, a3y = 0.f;

    int e = g_start[i];
    int end = e + (int)(g_packed[i] >> 40);
    for (; e + 4 <= end; e += 4) {
        uint2 e0 = g_edge[e], e1 = g_edge[e + 1], e2 = g_edge[e + 2], e3 = g_edge[e + 3];
        float2 v0 = __half22float2(g_Shw[(size_t)e0.x * 32 + lane]);
        float2 v1 = __half22float2(g_Shw[(size_t)e1.x * 32 + lane]);
        float2 v2 = __half22float2(g_Shw[(size_t)e2.x * 32 + lane]);
        float2 v3 = __half22float2(g_Shw[(size_t)e3.x * 32 + lane]);
        float n0 = __uint_as_float(e0.y), n1 = __uint_as_float(e1.y);
        float n2 = __uint_as_float(e2.y), n3 = __uint_as_float(e3.y);
        ax  += n0 * v0.x; ay  += n0 * v0.y;
        a1x += n1 * v1.x; a1y += n1 * v1.y;
        a2x += n2 * v2.x; a2y += n2 * v2.y;
        a3x += n3 * v3.x; a3y += n3 * v3.y;
    }
    for (; e < end; e++) {
        uint2 e0 = g_edge[e];
        float2 v0 = __half22float2(g_Shw[(size_t)e0.x * 32 + lane]);
        float n0 = __uint_as_float(e0.y);
        ax += n0 * v0.x; ay += n0 * v0.y;
    }
    ax += a1x + a2x + a3x;
    ay += a1y + a2y + a3y;

    float2 bb = reinterpret_cast<const float2*>(bias)[lane];
    ax += bb.x; ay += bb.y;
    if (resid >= 0) {
        float2 r = reinterpret_cast<const float2*>(g_H[resid])[(size_t)i * 32 + lane];
        ax += r.x; ay += r.y;
    }
    ax = fmaxf(ax, 0.f); ay = fmaxf(ay, 0.f);
    reinterpret_cast<float2*>(g_H[dst])[(size_t)i * 32 + lane] = make_float2(ax, ay);
}

// ---------------------------------------------------------------------------
// Layer-3 aggregation fused with final GEMV: computes h3 in regs, dots with Wf,
// writes only g_F (h3 never materialized).
// ---------------------------------------------------------------------------
__global__ void __launch_bounds__(256) agg3_kernel(const float* __restrict__ bias,
                                                   int resid,
                                                   const float* __restrict__ Wf, int n)
{
    int wid = (blockIdx.x * blockDim.x + threadIdx.x) >> 5;
    int lane = threadIdx.x & 31;
    if (wid >= n) return;
    int i = wid;

    float di = g_dinv[i];
    float selfn = di * di;
    float2 v = __half22float2(g_Shw[(size_t)i * 32 + lane]);
    float ax = selfn * v.x, ay = selfn * v.y;
    float a1x = 0.f, a1y = 0.f, a2x = 0.f, a2y = 0.f, a3x = 0.f, a3y = 0.f;

    int e = g_start[i];
    int end = e + (int)(g_packed[i] >> 40);
    for (; e + 4 <= end; e += 4) {
        uint2 e0 = g_edge[e], e1 = g_edge[e + 1], e2 = g_edge[e + 2], e3 = g_edge[e + 3];
        float2 v0 = __half22float2(g_Shw[(size_t)e0.x * 32 + lane]);
        float2 v1 = __half22float2(g_Shw[(size_t)e1.x * 32 + lane]);
        float2 v2 = __half22float2(g_Shw[(size_t)e2.x * 32 + lane]);
        float2 v3 = __half22float2(g_Shw[(size_t)e3.x * 32 + lane]);
        float n0 = __uint_as_float(e0.y), n1 = __uint_as_float(e1.y);
        float n2 = __uint_as_float(e2.y), n3 = __uint_as_float(e3.y);
        ax  += n0 * v0.x; ay  += n0 * v0.y;
        a1x += n1 * v1.x; a1y += n1 * v1.y;
        a2x += n2 * v2.x; a2y += n2 * v2.y;
        a3x += n3 * v3.x; a3y += n3 * v3.y;
    }
    for (; e < end; e++) {
        uint2 e0 = g_edge[e];
        float2 v0 = __half22float2(g_Shw[(size_t)e0.x * 32 + lane]);
        float n0 = __uint_as_float(e0.y);
        ax += n0 * v0.x; ay += n0 * v0.y;
    }
    ax += a1x + a2x + a3x;
    ay += a1y + a2y + a3y;

    float2 bb = reinterpret_cast<const float2*>(bias)[lane];
    ax += bb.x; ay += bb.y;
    if (resid >= 0) {
        float2 r = reinterpret_cast<const float2*>(g_H[resid])[(size_t)i * 32 + lane];
        ax += r.x; ay += r.y;
    }
    ax = fmaxf(ax, 0.f); ay = fmaxf(ay, 0.f);   // h3 lanes

    float2 wf = reinterpret_cast<const float2*>(Wf)[lane];
    float p = ax * wf.x + ay * wf.y;
#pragma unroll
    for (int o = 16; o; o >>= 1) p += __shfl_xor_sync(0xffffffffu, p, o);
    if (lane == 0) g_F[i] = p;
}

// ---------------------------------------------------------------------------
// Final scalar aggregation: out[i] = sum_e nm*F[src] + dinv^2*F[i] + bf
// ---------------------------------------------------------------------------
__global__ void agg_final_kernel(const float* __restrict__ bf,
                                 float* __restrict__ out, int n)
{
    int i = blockIdx.x * blockDim.x + threadIdx.x;
    if (i >= n) return;
    float di = g_dinv[i];
    float acc = di * di * g_F[i];
    float a1 = 0.f, a2 = 0.f, a3 = 0.f;
    int e = g_start[i];
    int end = e + (int)(g_packed[i] >> 40);
    for (; e + 4 <= end; e += 4) {
        uint2 e0 = g_edge[e], e1 = g_edge[e + 1], e2 = g_edge[e + 2], e3 = g_edge[e + 3];
        acc += __uint_as_float(e0.y) * g_F[e0.x];
        a1  += __uint_as_float(e1.y) * g_F[e1.x];
        a2  += __uint_as_float(e2.y) * g_F[e2.x];
        a3  += __uint_as_float(e3.y) * g_F[e3.x];
    }
    for (; e < end; e++) {
        uint2 e0 = g_edge[e];
        acc += __uint_as_float(e0.y) * g_F[e0.x];
    }
    out[i] = acc + a1 + a2 + a3 + bf[0];
}

// ---------------------------------------------------------------------------
// Launch
// ---------------------------------------------------------------------------
extern "C" void kernel_launch(void* const* d_in, const int* in_sizes, int n_in,
                              void* d_out, int out_size)
{
    const float* x    = (const float*)d_in[0];
    const void*  ei   = d_in[1];
    const float* ew   = (const float*)d_in[2];
    const float* W_in = (const float*)d_in[4];
    const float* b_in = (const float*)d_in[5];
    const float* W1   = (const float*)d_in[6];
    const float* b1   = (const float*)d_in[7];
    const float* W2   = (const float*)d_in[8];
    const float* b2   = (const float*)d_in[9];
    const float* Wf   = (const float*)d_in[10];
    const float* bf   = (const float*)d_in[11];
    float* out = (float*)d_out;

    int n = in_sizes[0] / 64;
    int E = in_sizes[2];

    int nbN  = (n + 255) / 256;
    int nbE  = (E + 255) / 256;
    int nbSc = (n + 1023) / 1024;     // <= 128
    int nbAg = (n + 7) / 8;           // warp per node
    int nbGm = (n + 255) / 256;

    // --- probe + norm + CSR build ---
    init_kernel<<<nbN, 256>>>(ei, E, n);
    hist_kernel<<<nbE, 256>>>(ei, ew, E, n);
    scan1_kernel<<<nbSc, 256>>>(n);
    scan23_kernel<<<nbN, 256>>>(n, nbSc);
    build_kernel<<<nbE, 256>>>(ei, ew, E, n);

    // --- layer 1: h1 = relu(conv(x)) -> H[0] ---
    gemm64_kernel<<<nbGm, 256>>>(x, 0, W_in, n);
    agg_kernel<<<nbAg, 256>>>(b_in, -1, 0, n);

    // --- layer 2: h2 = relu(conv(h1) + h1) -> H[1] ---
    gemm64_kernel<<<nbGm, 256>>>(nullptr, 0, W1, n);
    agg_kernel<<<nbAg, 256>>>(b1, 0, 1, n);

    // --- layer 3 + final gemv: F = (relu(conv(h2)+h2)) @ Wf ---
    gemm64_kernel<<<nbGm, 256>>>(nullptr, 1, W2, n);
    agg3_kernel<<<nbAg, 256>>>(b2, 1, Wf, n);

    // --- final aggregation ---
    agg_final_kernel<<<nbN, 256>>>(bf, out, n);
}